// round 6
// baseline (speedup 1.0000x reference)
#include <cuda_runtime.h>
#include <cstdint>

#define N1 16384
#define N2 16384
#define GRID 128
#define NCELL (GRID * GRID)
#define RLO (-6.0f)
#define RANGE 12.0f
#define CELLW (RANGE / (float)GRID)      // 0.09375, exact in fp32
#define INVCELL ((float)GRID / RANGE)
#define BINTHREADS 1024
#define QBLOCKS 128
#define QTHREADS 128

// Cell counts: must be zero at kernel entry; statically zero-initialized and
// re-zeroed inside bin_kernel after the scan consumes them (replay invariant).
__device__ int g_cnt[NCELL];
// After scan: exclusive prefix. After scatter: inclusive end per cell.
// start(c) = (c>0) ? g_ofs[c-1] : 0.   Rewritten fresh every launch.
__device__ int g_ofs[NCELL];
__device__ float2 g_spts[N2];
__device__ float g_bsum[QBLOCKS];

__device__ __forceinline__ int cell_of(float x, float y) {
    int ix = (int)((x - RLO) * INVCELL);
    int iy = (int)((y - RLO) * INVCELL);
    ix = max(0, min(GRID - 1, ix));
    iy = max(0, min(GRID - 1, iy));
    return iy * GRID + ix;
}

// ── Kernel 1: bin pos2 (count -> scan -> scatter), single block ──────────────
__global__ __launch_bounds__(BINTHREADS)
void bin_kernel(const float2* __restrict__ pos2) {
    __shared__ int sc[BINTHREADS];
    const int t = threadIdx.x;

    // Phase 1: count (global atomics; g_cnt is zero on entry by invariant)
#pragma unroll
    for (int i = t; i < N2; i += BINTHREADS) {
        float2 p = pos2[i];
        atomicAdd(&g_cnt[cell_of(p.x, p.y)], 1);
    }
    __syncthreads();

    // Phase 2: exclusive scan over 16384 cells (16 cells/thread + block scan),
    // write g_ofs, re-zero g_cnt for the next replay.
    const int base = t * (NCELL / BINTHREADS);   // 16 cells per thread
    int loc[NCELL / BINTHREADS];
    int s = 0;
#pragma unroll
    for (int k = 0; k < NCELL / BINTHREADS; k++) {
        loc[k] = s;
        s += g_cnt[base + k];
    }
    sc[t] = s;
    __syncthreads();
    for (int off = 1; off < BINTHREADS; off <<= 1) {
        int v = (t >= off) ? sc[t - off] : 0;
        __syncthreads();
        sc[t] += v;
        __syncthreads();
    }
    int excl = sc[t] - s;
#pragma unroll
    for (int k = 0; k < NCELL / BINTHREADS; k++) {
        g_ofs[base + k] = excl + loc[k];
        g_cnt[base + k] = 0;
    }
    __syncthreads();

    // Phase 3: scatter (atomicAdd turns g_ofs into inclusive ends)
#pragma unroll
    for (int i = t; i < N2; i += BINTHREADS) {
        float2 p = pos2[i];
        int c = cell_of(p.x, p.y);
        int pos = atomicAdd(&g_ofs[c], 1);
        g_spts[pos] = p;
    }
}

// Scan all points in the contiguous cell range [c0, c1] (row-major contiguous).
__device__ __forceinline__ void scan_range(int c0, int c1, float qx, float qy,
                                           float& m) {
    int s = (c0 > 0) ? g_ofs[c0 - 1] : 0;
    int e = g_ofs[c1];
    for (int i = s; i < e; i++) {
        float2 p = g_spts[i];
        float dx = qx - p.x;
        float dy = qy - p.y;
        float d2 = fmaf(dx, dx, dy * dy);
        m = fminf(m, d2);
    }
}

// ── Kernel 2: per-pos1 ring search + block partial sum ───────────────────────
__global__ __launch_bounds__(QTHREADS)
void query_kernel(const float2* __restrict__ pos1) {
    __shared__ float red[QTHREADS];
    const int t = blockIdx.x * QTHREADS + threadIdx.x;

    float2 q = pos1[t];
    int ix = max(0, min(GRID - 1, (int)((q.x - RLO) * INVCELL)));
    int iy = max(0, min(GRID - 1, (int)((q.y - RLO) * INVCELL)));

    float m = __uint_as_float(0x7f800000u);  // +inf

    for (int r = 0; r < GRID; r++) {
        if (r >= 1) {
            float b = (float)(r - 1) * CELLW;   // valid lower bound for ring >= r
            if (b * b >= m) break;
        }
        int x0 = max(ix - r, 0), x1 = min(ix + r, GRID - 1);
        int y0 = max(iy - r, 0), y1 = min(iy + r, GRID - 1);
        if (r == 0) {
            scan_range(iy * GRID + ix, iy * GRID + ix, q.x, q.y, m);
        } else {
            if (iy - r >= 0)         // top row (contiguous cells -> one range)
                scan_range((iy - r) * GRID + x0, (iy - r) * GRID + x1, q.x, q.y, m);
            if (iy + r <= GRID - 1)  // bottom row
                scan_range((iy + r) * GRID + x0, (iy + r) * GRID + x1, q.x, q.y, m);
            int yy0 = max(iy - r + 1, 0), yy1 = min(iy + r - 1, GRID - 1);
            if (ix - r >= 0)         // left column (cell by cell)
                for (int yy = yy0; yy <= yy1; yy++)
                    scan_range(yy * GRID + (ix - r), yy * GRID + (ix - r), q.x, q.y, m);
            if (ix + r <= GRID - 1)  // right column
                for (int yy = yy0; yy <= yy1; yy++)
                    scan_range(yy * GRID + (ix + r), yy * GRID + (ix + r), q.x, q.y, m);
        }
    }

    red[threadIdx.x] = sqrtf(m);
    __syncthreads();
    for (int w = QTHREADS / 2; w > 0; w >>= 1) {
        if (threadIdx.x < w) red[threadIdx.x] += red[threadIdx.x + w];
        __syncthreads();
    }
    if (threadIdx.x == 0) g_bsum[blockIdx.x] = red[0];
}

// ── Kernel 3: final mean ─────────────────────────────────────────────────────
__global__ void sum_kernel(float* __restrict__ out) {
    __shared__ float red[QBLOCKS];
    const int t = threadIdx.x;
    red[t] = g_bsum[t];
    __syncthreads();
    for (int w = QBLOCKS / 2; w > 0; w >>= 1) {
        if (t < w) red[t] += red[t + w];
        __syncthreads();
    }
    if (t == 0) out[0] = red[0] * (1.0f / (float)N1);
}

extern "C" void kernel_launch(void* const* d_in, const int* in_sizes, int n_in,
                              void* d_out, int out_size) {
    const float2* pos1 = (const float2*)d_in[0];
    const float2* pos2 = (const float2*)d_in[1];
    float* out = (float*)d_out;

    bin_kernel<<<1, BINTHREADS>>>(pos2);
    query_kernel<<<QBLOCKS, QTHREADS>>>(pos1);
    sum_kernel<<<1, QBLOCKS>>>(out);
}

// round 8
// speedup vs baseline: 1.4568x; 1.4568x over previous
#include <cuda_runtime.h>
#include <cstdint>

#define N1 16384
#define N2 16384
#define GRID 128
#define NCELL (GRID * GRID)
#define RLO (-6.0f)
#define RANGE 12.0f
#define CELLW (RANGE / (float)GRID)      // 0.09375, exact in fp32
#define INVCELL ((float)GRID / RANGE)
#define QBLOCKS 128
#define QTHREADS 128
#define FINF __uint_as_float(0x7f800000u)

// Cell counts: zero at kernel entry (static zero init; scan_kernel re-zeroes
// after consuming -> replay invariant).
__device__ int g_cnt[NCELL];
// After scan: exclusive prefix. After scatter: inclusive end per cell.
// start(c) = (c>0) ? g_ofs[c-1] : 0.  Rewritten fresh every launch.
__device__ int g_ofs[NCELL];
__device__ float2 g_spts[N2];
__device__ float g_bsum[QBLOCKS];
__device__ unsigned int g_done = 0;

__device__ __forceinline__ int clampi(int v, int lo, int hi) {
    return max(lo, min(hi, v));
}

__device__ __forceinline__ int cell_of(float x, float y) {
    int ix = clampi((int)((x - RLO) * INVCELL), 0, GRID - 1);
    int iy = clampi((int)((y - RLO) * INVCELL), 0, GRID - 1);
    return iy * GRID + ix;
}

// ── Kernel 1: count (parallel over 64 blocks; atomics spread over 16k cells) ──
__global__ __launch_bounds__(256)
void count_kernel(const float2* __restrict__ pos2) {
    int i = blockIdx.x * 256 + threadIdx.x;
    float2 p = pos2[i];
    atomicAdd(&g_cnt[cell_of(p.x, p.y)], 1);
}

// ── Kernel 2: exclusive scan over 16384 cells (single block), re-zero g_cnt ──
__global__ __launch_bounds__(1024)
void scan_kernel() {
    __shared__ int sc[1024];
    const int t = threadIdx.x;
    const int base = t * (NCELL / 1024);   // 16 cells per thread
    int loc[NCELL / 1024];
    int s = 0;
#pragma unroll
    for (int k = 0; k < NCELL / 1024; k++) {
        loc[k] = s;
        s += g_cnt[base + k];
    }
    sc[t] = s;
    __syncthreads();
    for (int off = 1; off < 1024; off <<= 1) {
        int v = (t >= off) ? sc[t - off] : 0;
        __syncthreads();
        sc[t] += v;
        __syncthreads();
    }
    int excl = sc[t] - s;
#pragma unroll
    for (int k = 0; k < NCELL / 1024; k++) {
        g_ofs[base + k] = excl + loc[k];
        g_cnt[base + k] = 0;               // restore zero invariant for replay
    }
}

// ── Kernel 3: scatter (atomicAdd turns g_ofs into inclusive ends) ────────────
__global__ __launch_bounds__(256)
void scatter_kernel(const float2* __restrict__ pos2) {
    int i = blockIdx.x * 256 + threadIdx.x;
    float2 p = pos2[i];
    int c = cell_of(p.x, p.y);
    int pos = atomicAdd(&g_ofs[c], 1);
    g_spts[pos] = p;
}

__device__ __forceinline__ void scan_pts(int s, int e, float qx, float qy,
                                         float& m) {
    for (int i = s; i < e; i++) {
        float2 p = g_spts[i];
        float dx = qx - p.x;
        float dy = qy - p.y;
        m = fminf(m, fmaf(dx, dx, dy * dy));
    }
}

__device__ __forceinline__ void scan_cells(int c0, int c1, float qx, float qy,
                                           float& m) {
    int s = (c0 > 0) ? g_ofs[c0 - 1] : 0;
    scan_pts(s, g_ofs[c1], qx, qy, m);
}

// ── Kernel 4: per-pos1 query (3x3 fast path + ring fallback) + fused mean ────
__global__ __launch_bounds__(QTHREADS)
void query_kernel(const float2* __restrict__ pos1, float* __restrict__ out) {
    __shared__ float red[QTHREADS];
    __shared__ unsigned int s_last;
    const int t = blockIdx.x * QTHREADS + threadIdx.x;

    float2 q = pos1[t];
    int ix = clampi((int)((q.x - RLO) * INVCELL), 0, GRID - 1);
    int iy = clampi((int)((q.y - RLO) * INVCELL), 0, GRID - 1);

    float m = FINF;

    // Fast path: 3x3 neighborhood. All 6 range offsets loaded up front (batched).
    int x0 = max(ix - 1, 0), x1 = min(ix + 1, GRID - 1);
    int y0 = max(iy - 1, 0), y1 = min(iy + 1, GRID - 1);
    int nrows = y1 - y0 + 1;
    int rs[3], re[3];
#pragma unroll
    for (int k = 0; k < 3; k++) {
        int yy = min(y0 + k, y1);
        int c0 = yy * GRID + x0;
        rs[k] = (c0 > 0) ? g_ofs[c0 - 1] : 0;
        re[k] = g_ofs[yy * GRID + x1];
    }
#pragma unroll
    for (int k = 0; k < 3; k++) {
        if (k < nrows) scan_pts(rs[k], re[k], q.x, q.y, m);
    }

    // Exact bound: distance from q to the scanned-rect boundary. Edges at the
    // domain border are +inf (no unscanned cells there; clamped outliers are
    // inside the scanned cells, and their true distance >= cell-based bound).
    float bx0 = (x0 == 0)        ? FINF : q.x - (RLO + (float)x0 * CELLW);
    float bx1 = (x1 == GRID - 1) ? FINF : (RLO + (float)(x1 + 1) * CELLW) - q.x;
    float by0 = (y0 == 0)        ? FINF : q.y - (RLO + (float)y0 * CELLW);
    float by1 = (y1 == GRID - 1) ? FINF : (RLO + (float)(y1 + 1) * CELLW) - q.y;
    float b = fminf(fminf(bx0, bx1), fminf(by0, by1));

    if (b * b < m) {
        // Slow path: expand rings r = 2, 3, ... (rare).
        for (int r = 2; r < GRID; r++) {
            float lb = (float)(r - 1) * CELLW;   // lower bound for ring >= r
            if (lb * lb >= m) break;
            int xa = max(ix - r, 0), xb = min(ix + r, GRID - 1);
            if (iy - r >= 0)
                scan_cells((iy - r) * GRID + xa, (iy - r) * GRID + xb, q.x, q.y, m);
            if (iy + r <= GRID - 1)
                scan_cells((iy + r) * GRID + xa, (iy + r) * GRID + xb, q.x, q.y, m);
            int ya = max(iy - r + 1, 0), yb = min(iy + r - 1, GRID - 1);
            if (ix - r >= 0)
                for (int yy = ya; yy <= yb; yy++)
                    scan_cells(yy * GRID + (ix - r), yy * GRID + (ix - r), q.x, q.y, m);
            if (ix + r <= GRID - 1)
                for (int yy = ya; yy <= yb; yy++)
                    scan_cells(yy * GRID + (ix + r), yy * GRID + (ix + r), q.x, q.y, m);
        }
    }

    red[threadIdx.x] = sqrtf(m);
    __syncthreads();
    for (int w = QTHREADS / 2; w > 0; w >>= 1) {
        if (threadIdx.x < w) red[threadIdx.x] += red[threadIdx.x + w];
        __syncthreads();
    }
    if (threadIdx.x == 0) g_bsum[blockIdx.x] = red[0];

    // Done-counter tail: last block computes the mean.
    __threadfence();
    __syncthreads();
    if (threadIdx.x == 0) {
        unsigned int prev = atomicAdd(&g_done, 1u);
        s_last = (prev == (unsigned int)(QBLOCKS - 1)) ? 1u : 0u;
    }
    __syncthreads();
    if (s_last) {
        __threadfence();
        float v = __ldcg(&g_bsum[threadIdx.x]);   // QTHREADS == QBLOCKS
        red[threadIdx.x] = v;
        __syncthreads();
        for (int w = QTHREADS / 2; w > 0; w >>= 1) {
            if (threadIdx.x < w) red[threadIdx.x] += red[threadIdx.x + w];
            __syncthreads();
        }
        if (threadIdx.x == 0) {
            out[0] = red[0] * (1.0f / (float)N1);
            g_done = 0;   // reset for next replay
        }
    }
}

extern "C" void kernel_launch(void* const* d_in, const int* in_sizes, int n_in,
                              void* d_out, int out_size) {
    const float2* pos1 = (const float2*)d_in[0];
    const float2* pos2 = (const float2*)d_in[1];
    float* out = (float*)d_out;

    count_kernel<<<N2 / 256, 256>>>(pos2);
    scan_kernel<<<1, 1024>>>();
    scatter_kernel<<<N2 / 256, 256>>>(pos2);
    query_kernel<<<QBLOCKS, QTHREADS>>>(pos1, out);
}